// round 4
// baseline (speedup 1.0000x reference)
#include <cuda_runtime.h>

// DataWindowLoss: mean(|box5(x) - box5(y)|) with padding=4.
// Reduced to: single pass over d = x - y, separable 5x5 box (no /25 until the end),
// |.|-accumulate, one scalar out.
//
// x, y: [64, 1, 512, 512] fp32. Output of conv: [64, 1, 516, 516]; scalar mean.

#define BATCH   64
#define H       512
#define W       512
#define OW      516   // W + 4
#define OH      516   // H + 4
#define TR      86    // output rows per block (516 = 6 * 86)
#define NSTRIP  6
#define BLOCK   544   // 17 warps; threads [0,516) own output columns, [0,128) load rows
#define NWARPS  (BLOCK / 32)

__device__ double g_acc;

__global__ void zero_acc_kernel() { g_acc = 0.0; }

__global__ __launch_bounds__(BLOCK)
void box_loss_kernel(const float* __restrict__ x, const float* __restrict__ y) {
    // 4-zero pad on each side so horizontal sum needs no branches.
    __shared__ float sd[OW + 4];          // 520 floats
    __shared__ float warp_sums[NWARPS];

    const int tid = threadIdx.x;
    const int b   = blockIdx.y;
    const int o0  = blockIdx.x * TR;      // first output row of this strip

    const float* xb = x + (size_t)b * H * W;
    const float* yb = y + (size_t)b * H * W;

    if (tid < 4) { sd[tid] = 0.0f; sd[OW + tid] = 0.0f; }

    // Input rows needed: [o0-4, o0+TR-1] clamped to [0, H)
    int first_r = o0 - 4; if (first_r < 0) first_r = 0;
    int last_r  = o0 + TR - 1; if (last_r > H - 1) last_r = H - 1;

    // 2-deep register prefetch pipeline (threads 0..127 each load one float4
    // of x and y per row => MLP 4 per loading thread).
    float4 pxb[2], pyb[2];
    if (tid < 128) {
        {
            const float4* x4 = (const float4*)(xb + (size_t)first_r * W);
            const float4* y4 = (const float4*)(yb + (size_t)first_r * W);
            pxb[first_r & 1] = x4[tid];
            pyb[first_r & 1] = y4[tid];
        }
        if (first_r + 1 <= last_r) {
            int r1 = first_r + 1;
            const float4* x4 = (const float4*)(xb + (size_t)r1 * W);
            const float4* y4 = (const float4*)(yb + (size_t)r1 * W);
            pxb[r1 & 1] = x4[tid];
            pyb[r1 & 1] = y4[tid];
        }
    }

    float ring[5] = {0.f, 0.f, 0.f, 0.f, 0.f};
    float acc = 0.f;

    #pragma unroll 1
    for (int step = 0; step < TR + 4; ++step) {
        const int r = o0 - 4 + step;          // virtual input row (block-uniform)
        float s = 0.f;
        if (r >= 0 && r < H) {                // uniform branch: barrier-safe
            __syncthreads();                  // previous smem reads complete
            if (tid < 128) {
                const int p = r & 1;
                float4 dx;
                dx.x = pxb[p].x - pyb[p].x;
                dx.y = pxb[p].y - pyb[p].y;
                dx.z = pxb[p].z - pyb[p].z;
                dx.w = pxb[p].w - pyb[p].w;
                *(float4*)(&sd[4 + 4 * tid]) = dx;
                const int rn = r + 2;         // prefetch 2 rows ahead
                if (rn <= last_r) {
                    const float4* x4 = (const float4*)(xb + (size_t)rn * W);
                    const float4* y4 = (const float4*)(yb + (size_t)rn * W);
                    pxb[p] = x4[tid];         // rn & 1 == r & 1
                    pyb[p] = y4[tid];
                }
            }
            __syncthreads();
            if (tid < OW) {
                // horizontal 5-wide box (un-normalized); conflict-free smem reads
                s = sd[tid] + sd[tid + 1] + sd[tid + 2] + sd[tid + 3] + sd[tid + 4];
            }
        }
        ring[step % 5] = s;
        if (step >= 4) {
            // vertical 5-tall box, recomputed fresh (no incremental drift)
            float v = ring[0] + ring[1] + ring[2] + ring[3] + ring[4];
            if (tid < OW) acc += fabsf(v);
        }
    }

    // Block reduction
    #pragma unroll
    for (int off = 16; off; off >>= 1)
        acc += __shfl_xor_sync(0xffffffffu, acc, off);
    const int warp = tid >> 5, lane = tid & 31;
    if (lane == 0) warp_sums[warp] = acc;
    __syncthreads();
    if (tid == 0) {
        float t = 0.f;
        #pragma unroll
        for (int w = 0; w < NWARPS; ++w) t += warp_sums[w];
        atomicAdd(&g_acc, (double)t);
    }
}

__global__ void finalize_kernel(float* __restrict__ out) {
    out[0] = (float)(g_acc / 25.0 / ((double)BATCH * OH * OW));
}

extern "C" void kernel_launch(void* const* d_in, const int* in_sizes, int n_in,
                              void* d_out, int out_size) {
    (void)in_sizes; (void)n_in; (void)out_size;
    const float* x = (const float*)d_in[0];
    const float* y = (const float*)d_in[1];
    float* out = (float*)d_out;

    zero_acc_kernel<<<1, 1>>>();
    dim3 grid(NSTRIP, BATCH);
    box_loss_kernel<<<grid, BLOCK>>>(x, y);
    finalize_kernel<<<1, 1>>>(out);
}

// round 6
// speedup vs baseline: 7.8916x; 7.8916x over previous
#include <cuda_runtime.h>

// DataWindowLoss: mean(|box5(x) - box5(y)|), padding=4, x/y: [64,1,512,512] fp32.
// Reduction: box(x)-box(y) = box(x-y); 5x5 uniform box is separable; |c*s| = c*|s|.
// One streaming pass: diff -> horizontal 5-sum (smem) -> vertical 5-ring -> |.| accumulate.

#define BATCH   64
#define H       512
#define W       512
#define OW      516           // W + 4
#define OH      516
#define NSTRIP  6
#define TR      86            // output rows per block strip (6*86 = 516)
#define VR      (TR + 4)      // 90 virtual input rows per strip
#define CR      10            // rows per chunk (one barrier per chunk)
#define NCHUNK  (VR / CR)     // 9
#define BLOCK   640           // 20 warps; threads [0,516) own output columns
#define NWARPS  (BLOCK / 32)
#define ROWLEN  520           // 4 zero-pad + 512 diff + 4 zero-pad

__device__ double g_acc;

__global__ void zero_acc_kernel() { g_acc = 0.0; }

__global__ __launch_bounds__(BLOCK)
void box_loss_kernel(const float* __restrict__ x, const float* __restrict__ y) {
    __shared__ float sbuf[2][CR][ROWLEN];   // double-buffered diff rows, 41.6 KB
    __shared__ float wsum[NWARPS];

    const int tid = threadIdx.x;
    const int b   = blockIdx.y;
    const int o0  = blockIdx.x * TR;
    const int vr_base = o0 - 4;

    const float* xb = x + (size_t)b * H * W;
    const float* yb = y + (size_t)b * H * W;

    // Zero the 4-wide halo pads once (both buffers, all rows).
    if (tid < 2 * CR) {
        float* row = &sbuf[tid / CR][tid % CR][0];
        row[0] = row[1] = row[2] = row[3] = 0.f;
        row[516] = row[517] = row[518] = row[519] = 0.f;
    }

    // Register-staged chunk loads: per chunk each thread owns 2 float4 of x and y.
    // flat index f in [0, CR*128): row = f>>7, col4 = f&127.
    float4 rx[2], ry[2];
    #pragma unroll
    for (int i = 0; i < 2; ++i) {
        const int f = tid + i * BLOCK;
        const int row = f >> 7, col = (f & 127) << 2;
        const int gr = vr_base + row;
        if ((unsigned)gr < (unsigned)H) {
            rx[i] = __ldcs((const float4*)(xb + (size_t)gr * W + col));
            ry[i] = __ldcs((const float4*)(yb + (size_t)gr * W + col));
        } else {
            rx[i] = make_float4(0.f, 0.f, 0.f, 0.f);
            ry[i] = make_float4(0.f, 0.f, 0.f, 0.f);
        }
    }

    float ring[5] = {0.f, 0.f, 0.f, 0.f, 0.f};
    float acc = 0.f;

    #pragma unroll 1
    for (int chunk = 0; chunk < NCHUNK; ++chunk) {
        const int p = chunk & 1;

        // Commit staged registers (diff) to smem buffer p.
        #pragma unroll
        for (int i = 0; i < 2; ++i) {
            const int f = tid + i * BLOCK;
            const int row = f >> 7, col = (f & 127) << 2;
            float4 d;
            d.x = rx[i].x - ry[i].x;  d.y = rx[i].y - ry[i].y;
            d.z = rx[i].z - ry[i].z;  d.w = rx[i].w - ry[i].w;
            *(float4*)&sbuf[p][row][4 + col] = d;
        }

        // Prefetch next chunk into registers (latency hidden by compute below).
        if (chunk + 1 < NCHUNK) {
            const int vr0n = vr_base + (chunk + 1) * CR;
            #pragma unroll
            for (int i = 0; i < 2; ++i) {
                const int f = tid + i * BLOCK;
                const int row = f >> 7, col = (f & 127) << 2;
                const int gr = vr0n + row;
                if ((unsigned)gr < (unsigned)H) {
                    rx[i] = __ldcs((const float4*)(xb + (size_t)gr * W + col));
                    ry[i] = __ldcs((const float4*)(yb + (size_t)gr * W + col));
                } else {
                    rx[i] = make_float4(0.f, 0.f, 0.f, 0.f);
                    ry[i] = make_float4(0.f, 0.f, 0.f, 0.f);
                }
            }
        }

        __syncthreads();   // single barrier per chunk

        // Consume 10 rows: horizontal 5-sum from smem, vertical 5-ring in regs.
        #pragma unroll
        for (int rr = 0; rr < CR; ++rr) {
            float s = 0.f;
            if (tid < OW) {
                const float* q = &sbuf[p][rr][tid];
                s = q[0] + q[1] + q[2] + q[3] + q[4];
            }
            ring[rr % 5] = s;    // CR ≡ 0 mod 5 ⇒ slot is compile-time per rr
            const int step = chunk * CR + rr;
            if (step >= 4)       // output row = o0 + step - 4
                acc += fabsf(ring[0] + ring[1] + ring[2] + ring[3] + ring[4]);
        }
        // No trailing barrier needed: next iteration's STS targets the other
        // buffer; reuse of this buffer is fenced by the next chunk's barrier.
    }

    // Block reduction -> one double atomic per block (384 total).
    #pragma unroll
    for (int off = 16; off; off >>= 1)
        acc += __shfl_xor_sync(0xffffffffu, acc, off);
    const int warp = tid >> 5, lane = tid & 31;
    if (lane == 0) wsum[warp] = acc;
    __syncthreads();
    if (tid == 0) {
        float t = 0.f;
        #pragma unroll
        for (int w = 0; w < NWARPS; ++w) t += wsum[w];
        atomicAdd(&g_acc, (double)t);
    }
}

__global__ void finalize_kernel(float* __restrict__ out) {
    out[0] = (float)(g_acc / 25.0 / ((double)BATCH * OH * OW));
}

extern "C" void kernel_launch(void* const* d_in, const int* in_sizes, int n_in,
                              void* d_out, int out_size) {
    (void)in_sizes; (void)n_in; (void)out_size;
    const float* x = (const float*)d_in[0];
    const float* y = (const float*)d_in[1];
    float* out = (float*)d_out;

    zero_acc_kernel<<<1, 1>>>();
    dim3 grid(NSTRIP, BATCH);
    box_loss_kernel<<<grid, BLOCK>>>(x, y);
    finalize_kernel<<<1, 1>>>(out);
}

// round 9
// speedup vs baseline: 8.7426x; 1.1078x over previous
#include <cuda_runtime.h>

// DataWindowLoss: mean(|box5(x) - box5(y)|), padding=4, x/y: [64,1,512,512] fp32.
// box(x)-box(y) = box(x-y); 5x5 uniform box is separable; |c*s| = c*|s|.
// Single kernel: balanced global-row partition over 296 blocks (one full wave
// at 2 blocks/SM), chunked double-buffered smem pipeline, fused finalize.

#define BATCH   64
#define H       512
#define W       512
#define OW      516
#define OH      516
#define G_ROWS  (BATCH * OH)        // 33024 global output rows
#define NB      296                 // 2 blocks/SM * 148 SMs: one balanced wave
#define BLOCK   768
#define NWARPS  (BLOCK / 32)        // 24
#define CR      6                   // rows/chunk: 6*128 float4 == 768 threads
#define ROWLEN  520                 // 4 zero-pad + 512 + 4 zero-pad

__device__ double   g_acc;          // zero at module load; reset by last block
__device__ unsigned g_count;

__global__ __launch_bounds__(BLOCK, 2)
void box_loss_kernel(const float* __restrict__ x, const float* __restrict__ y,
                     float* __restrict__ out) {
    __shared__ float sbuf[2][CR][ROWLEN];   // 24.96 KB double-buffered diff rows
    __shared__ float wsum[NWARPS];

    const int tid = threadIdx.x;
    const int row = tid >> 7;               // 0..5 : row within chunk this thread loads
    const int col = (tid & 127) << 2;       // 0..508 : float4 column

    // Zero the 4-wide halo pads once (both buffers, all rows).
    if (tid < 2 * CR) {
        float* r = &sbuf[tid / CR][tid % CR][0];
        r[0] = r[1] = r[2] = r[3] = 0.f;
        r[516] = r[517] = r[518] = r[519] = 0.f;
    }

    float acc = 0.f;

    // Balanced contiguous slice of the global (batch-major) output-row space.
    const int g0 = (int)((long long)blockIdx.x       * G_ROWS / NB);
    const int g1 = (int)((long long)(blockIdx.x + 1) * G_ROWS / NB);

    int g = g0;
    while (g < g1) {                         // per-batch segment (<=2 per block)
        const int b  = g / OH;
        const int s0 = g - b * OH;           // first output row in this batch
        int n = g1 - g;                      // rows in this segment
        if (n > OH - s0) n = OH - s0;
        const int VRseg  = n + 4;            // virtual input rows (incl. top halo)
        const int nchunk = (VRseg + CR - 1) / CR;
        const int vrb    = s0 - 4;
        const float* xb = x + (size_t)b * (H * W);
        const float* yb = y + (size_t)b * (H * W);

        __syncthreads();                     // smem reuse fence (segment start)

        // Preload chunk 0 into registers.
        float4 rx = make_float4(0.f, 0.f, 0.f, 0.f), ry = rx;
        {
            const int gr = vrb + row;
            if (row < VRseg && (unsigned)gr < (unsigned)H) {
                rx = __ldcs((const float4*)(xb + (size_t)gr * W + col));
                ry = __ldcs((const float4*)(yb + (size_t)gr * W + col));
            }
        }

        float r0 = 0.f, r1 = 0.f, r2 = 0.f, r3 = 0.f, r4 = 0.f;  // vertical ring

        #pragma unroll 1
        for (int c = 0; c < nchunk; ++c) {
            const int p = c & 1;

            // Commit staged diff to smem buffer p.
            {
                float4 d;
                d.x = rx.x - ry.x;  d.y = rx.y - ry.y;
                d.z = rx.z - ry.z;  d.w = rx.w - ry.w;
                *(float4*)&sbuf[p][row][4 + col] = d;
            }

            // Prefetch chunk c+1 (hidden under this chunk's compute).
            rx = make_float4(0.f, 0.f, 0.f, 0.f); ry = rx;
            if (c + 1 < nchunk) {
                const int st = (c + 1) * CR + row;
                const int gr = vrb + st;
                if (st < VRseg && (unsigned)gr < (unsigned)H) {
                    rx = __ldcs((const float4*)(xb + (size_t)gr * W + col));
                    ry = __ldcs((const float4*)(yb + (size_t)gr * W + col));
                }
            }

            __syncthreads();                 // one barrier per chunk

            // Consume CR rows: horizontal 5-sum from smem, vertical 5-shift ring.
            const int base = c * CR;
            #pragma unroll
            for (int rr = 0; rr < CR; ++rr) {
                float s = 0.f;
                if (tid < OW) {
                    const float* q = &sbuf[p][rr][tid];
                    s = q[0] + q[1] + q[2] + q[3] + q[4];
                }
                r0 = r1; r1 = r2; r2 = r3; r3 = r4; r4 = s;
                const int step = base + rr;
                if (step >= 4 && step < VRseg)
                    acc += fabsf(r0 + r1 + r2 + r3 + r4);
            }
            // Double buffering: next STS hits the other buffer; reuse of this
            // one is fenced by the next chunk's barrier.
        }
        g += n;
    }

    // Block reduction.
    #pragma unroll
    for (int off = 16; off; off >>= 1)
        acc += __shfl_xor_sync(0xffffffffu, acc, off);
    if ((tid & 31) == 0) wsum[tid >> 5] = acc;
    __syncthreads();
    if (tid == 0) {
        float t = 0.f;
        #pragma unroll
        for (int w = 0; w < NWARPS; ++w) t += wsum[w];
        atomicAdd(&g_acc, (double)t);
        __threadfence();
        const unsigned ticket = atomicAdd(&g_count, 1u);
        if (ticket == NB - 1) {              // last block finalizes + resets
            const double total = atomicAdd(&g_acc, 0.0);
            out[0] = (float)(total / 25.0 / ((double)BATCH * OH * OW));
            g_acc = 0.0;
            __threadfence();
            g_count = 0u;
        }
    }
}

extern "C" void kernel_launch(void* const* d_in, const int* in_sizes, int n_in,
                              void* d_out, int out_size) {
    (void)in_sizes; (void)n_in; (void)out_size;
    const float* x = (const float*)d_in[0];
    const float* y = (const float*)d_in[1];
    float* out = (float*)d_out;
    box_loss_kernel<<<NB, BLOCK>>>(x, y, out);
}